// round 9
// baseline (speedup 1.0000x reference)
#include <cuda_runtime.h>
#include <math.h>

typedef unsigned int u32;
typedef signed char s8;

#define H 4096
#define IDIM 5632
#define NE 8
#define T 4096
#define NSLOTS (T * 2)
#define BM 128
#define BN 64
#define BK 64
#define STAGE 24576
#define SMEMSZ (2048 + 2 * STAGE)

// ---------------- scratch (device globals; allocation-free) ----------------
__device__ float g_tmp[(size_t)NSLOTS * IDIM];
__device__ float g_act[(size_t)NSLOTS * IDIM];
__device__ s8    g_x1[(size_t)T * H];
__device__ s8    g_x0[(size_t)T * H];
__device__ s8    g_wg1[(size_t)NE * IDIM * H];
__device__ s8    g_wg0[(size_t)NE * IDIM * H];
__device__ s8    g_wu1[(size_t)NE * IDIM * H];
__device__ s8    g_wu0[(size_t)NE * IDIM * H];
__device__ s8    g_wd1[(size_t)NE * H * IDIM];
__device__ s8    g_wd0[(size_t)NE * H * IDIM];
__device__ s8    g_a1[(size_t)NSLOTS * IDIM];
__device__ s8    g_a0[(size_t)NSLOTS * IDIM];
__device__ float g_sx[T];
__device__ float g_swg[NE * IDIM];
__device__ float g_swu[NE * IDIM];
__device__ float g_swd[NE * H];
__device__ float g_sact[NSLOTS];
__device__ int   g_counts[NE];
__device__ int   g_offsets[NE];
__device__ int   g_cursor[NE];
__device__ int   g_topi[T * 2];
__device__ float g_topw[T * 2];
__device__ int   g_tok[NSLOTS];
__device__ float g_sw[NSLOTS];
__device__ float g_psum[NE];
__device__ float g_zsum;

// ---------------- helpers ----------------
__device__ __forceinline__ u32 smem_u32(const void* p) {
    u32 a;
    asm("{ .reg .u64 t; cvta.to.shared.u64 t, %1; cvt.u32.u64 %0, t; }" : "=r"(a) : "l"(p));
    return a;
}
// tile rows are 64 bytes = 4 chunks of 16B; XOR swizzle (same geometry as R8)
__device__ __forceinline__ u32 swoff(int row, int ch) {
    return (u32)(row * 64 + ((ch ^ ((row >> 1) & 3)) << 4));
}
__device__ __forceinline__ void st16(u32 a, uint4 v) {
    asm volatile("st.shared.v4.b32 [%0], {%1,%2,%3,%4};"
                 :: "r"(a), "r"(v.x), "r"(v.y), "r"(v.z), "r"(v.w) : "memory");
}
#define LDSM4(R, A)                                                             \
    asm volatile("ldmatrix.sync.aligned.m8n8.x4.shared.b16 {%0,%1,%2,%3}, [%4];" \
        : "=r"((R)[0]), "=r"((R)[1]), "=r"((R)[2]), "=r"((R)[3]) : "r"(A))

__device__ __forceinline__ void imma(int* d, const u32* a, const u32* b) {
    asm volatile(
        "mma.sync.aligned.m16n8k32.row.col.s32.s8.s8.s32 "
        "{%0,%1,%2,%3},{%4,%5,%6,%7},{%8,%9},{%0,%1,%2,%3};"
        : "+r"(d[0]), "+r"(d[1]), "+r"(d[2]), "+r"(d[3])
        : "r"(a[0]), "r"(a[1]), "r"(a[2]), "r"(a[3]), "r"(b[0]), "r"(b[1]));
}
__device__ __forceinline__ u32 pack4(int a, int b, int c, int d) {
    return (u32)(a & 255) | ((u32)(b & 255) << 8) | ((u32)(c & 255) << 16) | ((u32)(d & 255) << 24);
}

// ---------------- small kernels ----------------
__global__ void reset_kernel() {
    int i = threadIdx.x;
    if (i < NE) { g_counts[i] = 0; g_cursor[i] = 0; g_psum[i] = 0.f; }
    if (i == 0) g_zsum = 0.f;
}

__global__ void router_kernel(const float* __restrict__ x,
                              const float* __restrict__ Wgate) {
    int t = blockIdx.x;
    const float* xr = x + (size_t)t * H;
    float p[NE];
#pragma unroll
    for (int e = 0; e < NE; ++e) p[e] = 0.f;
    for (int c = threadIdx.x; c < H; c += blockDim.x) {
        float xv = xr[c];
#pragma unroll
        for (int e = 0; e < NE; ++e) p[e] += xv * Wgate[e * H + c];
    }
    __shared__ float sm[NE][128];
#pragma unroll
    for (int e = 0; e < NE; ++e) sm[e][threadIdx.x] = p[e];
    __syncthreads();
    for (int s = 64; s > 0; s >>= 1) {
        if (threadIdx.x < s)
#pragma unroll
            for (int e = 0; e < NE; ++e)
                sm[e][threadIdx.x] += sm[e][threadIdx.x + s];
        __syncthreads();
    }
    if (threadIdx.x == 0) {
        float lg[NE];
#pragma unroll
        for (int e = 0; e < NE; ++e) lg[e] = sm[e][0];
        float mx = lg[0];
#pragma unroll
        for (int e = 1; e < NE; ++e) mx = fmaxf(mx, lg[e]);
        float se = 0.f, pr[NE];
#pragma unroll
        for (int e = 0; e < NE; ++e) { pr[e] = expf(lg[e] - mx); se += pr[e]; }
        float inv = 1.f / se;
#pragma unroll
        for (int e = 0; e < NE; ++e) pr[e] *= inv;
        int i0 = 0;
#pragma unroll
        for (int e = 1; e < NE; ++e) if (pr[e] > pr[i0]) i0 = e;
        int i1 = (i0 == 0) ? 1 : 0;
#pragma unroll
        for (int e = 0; e < NE; ++e)
            if (e != i0 && pr[e] > pr[i1]) i1 = e;
        float w0 = pr[i0], w1 = pr[i1];
        float ws = 1.f / (w0 + w1);
        g_topi[2 * t] = i0;     g_topw[2 * t] = w0 * ws;
        g_topi[2 * t + 1] = i1; g_topw[2 * t + 1] = w1 * ws;
        atomicAdd(&g_counts[i0], 1);
        atomicAdd(&g_counts[i1], 1);
#pragma unroll
        for (int e = 0; e < NE; ++e) atomicAdd(&g_psum[e], pr[e]);
        float lse = mx + logf(se);
        atomicAdd(&g_zsum, lse * lse);
    }
}

__global__ void finalize_kernel(float* __restrict__ out, int out_size) {
    if (threadIdx.x == 0 && blockIdx.x == 0) {
        int off = 0;
        for (int e = 0; e < NE; ++e) { g_offsets[e] = off; g_cursor[e] = off; off += g_counts[e]; }
        float aux = 0.f;
        for (int e = 0; e < NE; ++e)
            aux += (g_psum[e] / (float)T) * ((float)g_counts[e] / (float)(T * 2));
        aux *= (float)NE;
        float z = g_zsum / (float)T;
        if (out_size > T * H) out[(size_t)T * H] = 0.02f * aux + 0.001f * z;
    }
}

__global__ void assign_kernel() {
    int t = blockIdx.x * blockDim.x + threadIdx.x;
    if (t >= T) return;
#pragma unroll
    for (int k = 0; k < 2; ++k) {
        int e = g_topi[2 * t + k];
        int s = atomicAdd(&g_cursor[e], 1);
        g_tok[s] = t;
        g_sw[s] = g_topw[2 * t + k];
    }
}

// ---------------- row quantization: v = s*(d1*128 + d0), s = rowmax/16256 ---
__global__ __launch_bounds__(256)
void quant_rows(const float* __restrict__ src, s8* __restrict__ d1,
                s8* __restrict__ d0, float* __restrict__ scl, int rowlen) {
    size_t row = blockIdx.x;
    const float* s = src + row * (size_t)rowlen;
    int tid = threadIdx.x;
    float m = 0.f;
    for (int i = tid * 4; i < rowlen; i += 1024) {
        float4 v = *(const float4*)(s + i);
        m = fmaxf(m, fmaxf(fmaxf(fabsf(v.x), fabsf(v.y)), fmaxf(fabsf(v.z), fabsf(v.w))));
    }
    __shared__ float red[8];
    for (int o = 16; o; o >>= 1) m = fmaxf(m, __shfl_xor_sync(~0u, m, o));
    if ((tid & 31) == 0) red[tid >> 5] = m;
    __syncthreads();
    if (tid == 0) {
        float t = red[0];
#pragma unroll
        for (int i = 1; i < 8; ++i) t = fmaxf(t, red[i]);
        red[0] = t;
        scl[row] = t * (1.f / 16256.f);
    }
    __syncthreads();
    float rm = red[0];
    float inv = rm > 0.f ? 16256.f / rm : 0.f;
    u32* p1 = (u32*)(d1 + row * (size_t)rowlen);
    u32* p0 = (u32*)(d0 + row * (size_t)rowlen);
    for (int i = tid * 4; i < rowlen; i += 1024) {
        float4 v = *(const float4*)(s + i);
        int h[4], l[4];
        float q;
        q = v.x * inv; h[0] = __float2int_rn(q * 0.0078125f); l[0] = __float2int_rn(fmaf(-128.f, (float)h[0], q));
        q = v.y * inv; h[1] = __float2int_rn(q * 0.0078125f); l[1] = __float2int_rn(fmaf(-128.f, (float)h[1], q));
        q = v.z * inv; h[2] = __float2int_rn(q * 0.0078125f); l[2] = __float2int_rn(fmaf(-128.f, (float)h[2], q));
        q = v.w * inv; h[3] = __float2int_rn(q * 0.0078125f); l[3] = __float2int_rn(fmaf(-128.f, (float)h[3], q));
        p1[i >> 2] = pack4(h[0], h[1], h[2], h[3]);
        p0[i >> 2] = pack4(l[0], l[1], l[2], l[3]);
    }
}

// ---------------- int8 2-digit MMA GEMM ----------------
// MODE 0: A=x digits (gather), B=Wg digits -> g_tmp
// MODE 1: A=x digits (gather), B=Wu digits -> g_act = silu(g_tmp)*u
// MODE 2: A=act digits,        B=Wd digits -> out[tok] += w * result (atomic)
template <int MODE>
__global__ __launch_bounds__(256)
void gemm_i8(const s8* __restrict__ A1, const s8* __restrict__ A0,
             const s8* __restrict__ B1p, const s8* __restrict__ B0p,
             const float* __restrict__ sA, const float* __restrict__ sB,
             float* __restrict__ outp) {
    constexpr int KD = (MODE == 2) ? IDIM : H;
    constexpr int ND = (MODE == 2) ? H : IDIM;
    constexpr int KT = KD / BK;

    int e = blockIdx.z;
    int cnt = g_counts[e];
    int m0 = blockIdx.x * BM;
    if (m0 >= cnt) return;
    int base = g_offsets[e];
    int n0 = blockIdx.y * BN;

    extern __shared__ char smem[];
    int*   rowsrc = (int*)smem;            // 128
    float* sas    = (float*)(smem + 512);  // 128
    float* sbs    = (float*)(smem + 1024); // 64
    u32 tiles = smem_u32(smem) + 2048;

    int tid = threadIdx.x, lane = tid & 31, wid = tid >> 5;
    int wm = wid & 3, wn = wid >> 2;

    if (tid < 128) {
        int r = m0 + tid;
        int slot = base + ((r < cnt) ? r : (cnt - 1));
        int rs = (MODE == 2) ? slot : g_tok[slot];
        rowsrc[tid] = rs;
        sas[tid] = sA[rs];
    }
    if (tid < 64) sbs[tid] = sB[e * ND + n0 + tid];
    __syncthreads();

    const s8* wB1 = B1p + (size_t)e * ND * KD + (size_t)n0 * KD;
    const s8* wB0 = B0p + (size_t)e * ND * KD + (size_t)n0 * KD;

    // loader mapping
    int arow = tid >> 1, ach = (tid & 1) * 2;
    size_t aoff = (size_t)rowsrc[arow] * KD + ach * 16;
    const s8* a1p = A1 + aoff;
    const s8* a0p = A0 + aoff;
    u32 sa0 = swoff(arow, ach), sa1 = swoff(arow, ach + 1);
    int brow = tid >> 2, bch = tid & 3;
    const s8* b1p = wB1 + (size_t)brow * KD + bch * 16;
    const s8* b0p = wB0 + (size_t)brow * KD + bch * 16;
    u32 sb0 = swoff(brow, bch);

    // preload stage 0: A1@0 A0@8192 B1@16384 B0@20480
    {
        uint4 v;
        v = *(const uint4*)a1p;        st16(tiles + sa0, v);
        v = *(const uint4*)(a1p + 16); st16(tiles + sa1, v);
        v = *(const uint4*)a0p;        st16(tiles + 8192 + sa0, v);
        v = *(const uint4*)(a0p + 16); st16(tiles + 8192 + sa1, v);
        v = *(const uint4*)b1p;        st16(tiles + 16384 + sb0, v);
        v = *(const uint4*)b0p;        st16(tiles + 20480 + sb0, v);
    }
    __syncthreads();

    int hh[2][4][4], xx[2][4][4];
#pragma unroll
    for (int i = 0; i < 2; ++i)
#pragma unroll
        for (int j = 0; j < 4; ++j)
#pragma unroll
            for (int c = 0; c < 4; ++c) { hh[i][j][c] = 0; xx[i][j][c] = 0; }

#pragma unroll 1
    for (int kt = 0; kt < KT; ++kt) {
        u32 stage = tiles + (kt & 1) * STAGE;
        uint4 pA1a, pA1b, pA0a, pA0b, pB1, pB0;
        bool pf = (kt + 1 < KT);
        if (pf) {
            int k0 = (kt + 1) * BK;
            pA1a = *(const uint4*)(a1p + k0);
            pA1b = *(const uint4*)(a1p + k0 + 16);
            pA0a = *(const uint4*)(a0p + k0);
            pA0b = *(const uint4*)(a0p + k0 + 16);
            pB1  = *(const uint4*)(b1p + k0);
            pB0  = *(const uint4*)(b0p + k0);
        }

#pragma unroll
        for (int ks = 0; ks < 2; ++ks) {
            u32 Af1[2][4], Af0[2][4], Bf1[4][2], Bf0[4][2];
#pragma unroll
            for (int mi = 0; mi < 2; ++mi) {
                int row = wm * 32 + mi * 16 + (lane & 15);
                int ch = ks * 2 + (lane >> 4);
                u32 off = swoff(row, ch);
                LDSM4(Af1[mi], stage + off);
                LDSM4(Af0[mi], stage + 8192 + off);
            }
#pragma unroll
            for (int g = 0; g < 2; ++g) {
                int row = wn * 32 + g * 16 + ((lane >> 4) << 3) + (lane & 7);
                int ch = ks * 2 + ((lane >> 3) & 1);
                u32 off = swoff(row, ch);
                u32 t[4];
                LDSM4(t, stage + 16384 + off);
                Bf1[2 * g][0] = t[0]; Bf1[2 * g][1] = t[1];
                Bf1[2 * g + 1][0] = t[2]; Bf1[2 * g + 1][1] = t[3];
                LDSM4(t, stage + 20480 + off);
                Bf0[2 * g][0] = t[0]; Bf0[2 * g][1] = t[1];
                Bf0[2 * g + 1][0] = t[2]; Bf0[2 * g + 1][1] = t[3];
            }
            // term-major: hh, then a1*b0, then a0*b1 (xx chains 8 apart)
#pragma unroll
            for (int mi = 0; mi < 2; ++mi)
#pragma unroll
                for (int ni = 0; ni < 4; ++ni)
                    imma(hh[mi][ni], Af1[mi], Bf1[ni]);
#pragma unroll
            for (int mi = 0; mi < 2; ++mi)
#pragma unroll
                for (int ni = 0; ni < 4; ++ni)
                    imma(xx[mi][ni], Af1[mi], Bf0[ni]);
#pragma unroll
            for (int mi = 0; mi < 2; ++mi)
#pragma unroll
                for (int ni = 0; ni < 4; ++ni)
                    imma(xx[mi][ni], Af0[mi], Bf1[ni]);
        }

        if (pf) {
            u32 ns = tiles + ((kt + 1) & 1) * STAGE;
            st16(ns + sa0, pA1a);
            st16(ns + sa1, pA1b);
            st16(ns + 8192 + sa0, pA0a);
            st16(ns + 8192 + sa1, pA0b);
            st16(ns + 16384 + sb0, pB1);
            st16(ns + 20480 + sb0, pB0);
        }
        __syncthreads();
    }

    // epilogue: val = sa*sb*(16384*hh + 128*xx)
    int rAl = wm * 32 + (lane >> 2);
    int cAl = wn * 32 + (lane & 3) * 2;
#pragma unroll
    for (int mi = 0; mi < 2; ++mi) {
#pragma unroll
        for (int ni = 0; ni < 4; ++ni) {
            int colL = cAl + ni * 8;
            float sb0v = sbs[colL], sb1v = sbs[colL + 1];
#pragma unroll
            for (int h = 0; h < 2; ++h) {
                int rl = rAl + mi * 16 + h * 8;
                int r = m0 + rl;
                if (r >= cnt) continue;
                float sav = sas[rl];
                float v0 = (16384.f * (float)hh[mi][ni][2 * h] + 128.f * (float)xx[mi][ni][2 * h]) * sav * sb0v;
                float v1 = (16384.f * (float)hh[mi][ni][2 * h + 1] + 128.f * (float)xx[mi][ni][2 * h + 1]) * sav * sb1v;
                int slot = base + r;
                int col = n0 + colL;
                if (MODE == 0) {
                    float2 o; o.x = v0; o.y = v1;
                    *(float2*)(g_tmp + (size_t)slot * IDIM + col) = o;
                } else if (MODE == 1) {
                    float2 g = *(const float2*)(g_tmp + (size_t)slot * IDIM + col);
                    float2 o;
                    o.x = g.x / (1.f + __expf(-g.x)) * v0;
                    o.y = g.y / (1.f + __expf(-g.y)) * v1;
                    *(float2*)(g_act + (size_t)slot * IDIM + col) = o;
                } else {
                    float w = g_sw[slot];
                    float* d = outp + (size_t)g_tok[slot] * H + col;
                    atomicAdd(d, w * v0);
                    atomicAdd(d + 1, w * v1);
                }
            }
        }
    }
}

// ---------------- launch ----------------
extern "C" void kernel_launch(void* const* d_in, const int* in_sizes, int n_in,
                              void* d_out, int out_size) {
    const float* x     = (const float*)d_in[0];
    const float* Wgate = (const float*)d_in[1];
    const float* Wg    = (const float*)d_in[2];
    const float* Wu    = (const float*)d_in[3];
    const float* Wd    = (const float*)d_in[4];
    float* out = (float*)d_out;

    cudaFuncSetAttribute(gemm_i8<0>, cudaFuncAttributeMaxDynamicSharedMemorySize, SMEMSZ);
    cudaFuncSetAttribute(gemm_i8<1>, cudaFuncAttributeMaxDynamicSharedMemorySize, SMEMSZ);
    cudaFuncSetAttribute(gemm_i8<2>, cudaFuncAttributeMaxDynamicSharedMemorySize, SMEMSZ);

    s8 *x1, *x0, *wg1, *wg0, *wu1, *wu0, *wd1, *wd0, *a1, *a0;
    float *sx, *swg, *swu, *swd, *sact;
    cudaGetSymbolAddress((void**)&x1, g_x1);   cudaGetSymbolAddress((void**)&x0, g_x0);
    cudaGetSymbolAddress((void**)&wg1, g_wg1); cudaGetSymbolAddress((void**)&wg0, g_wg0);
    cudaGetSymbolAddress((void**)&wu1, g_wu1); cudaGetSymbolAddress((void**)&wu0, g_wu0);
    cudaGetSymbolAddress((void**)&wd1, g_wd1); cudaGetSymbolAddress((void**)&wd0, g_wd0);
    cudaGetSymbolAddress((void**)&a1, g_a1);   cudaGetSymbolAddress((void**)&a0, g_a0);
    cudaGetSymbolAddress((void**)&sx, g_sx);
    cudaGetSymbolAddress((void**)&swg, g_swg); cudaGetSymbolAddress((void**)&swu, g_swu);
    cudaGetSymbolAddress((void**)&swd, g_swd); cudaGetSymbolAddress((void**)&sact, g_sact);
    float* tmpp; cudaGetSymbolAddress((void**)&tmpp, g_tmp);
    float* actp; cudaGetSymbolAddress((void**)&actp, g_act);

    cudaMemsetAsync(out, 0, (size_t)out_size * sizeof(float));
    reset_kernel<<<1, 32>>>();
    router_kernel<<<T, 128>>>(x, Wgate);
    finalize_kernel<<<1, 32>>>(out, out_size);
    assign_kernel<<<(T + 255) / 256, 256>>>();

    // quantization pre-passes
    quant_rows<<<T, 256>>>(x, x1, x0, sx, H);
    quant_rows<<<NE * IDIM, 256>>>(Wg, wg1, wg0, swg, H);
    quant_rows<<<NE * IDIM, 256>>>(Wu, wu1, wu0, swu, H);
    quant_rows<<<NE * H, 256>>>(Wd, wd1, wd0, swd, IDIM);

    dim3 g1(T / BM, IDIM / BN, NE);   // (32, 88, 8)
    gemm_i8<0><<<g1, 256, SMEMSZ>>>(x1, x0, wg1, wg0, sx, swg, out);
    gemm_i8<1><<<g1, 256, SMEMSZ>>>(x1, x0, wu1, wu0, sx, swu, out);

    quant_rows<<<NSLOTS, 256>>>(actp, a1, a0, sact, IDIM);

    dim3 g2(T / BM, H / BN, NE);      // (32, 64, 8)
    gemm_i8<2><<<g2, 256, SMEMSZ>>>(a1, a0, wd1, wd0, sact, swd, out);
}

// round 10
// speedup vs baseline: 3.5572x; 3.5572x over previous
#include <cuda_runtime.h>
#include <cuda_fp16.h>
#include <math.h>

typedef unsigned int u32;

#define H 4096
#define IDIM 5632
#define NE 8
#define T 4096
#define NSLOTS (T * 2)
#define BM 128
#define BN 128
#define BK 32
// stage: A 8KB @0 | B 8KB @8192  => 16KB; 2 stages
#define STAGE 16384
#define SMEMSZ (1024 + 2 * STAGE)

// ---------------- scratch (device globals; allocation-free) ----------------
__device__ float g_tmp[(size_t)NSLOTS * IDIM];   // raw gate values
__device__ float g_act[(size_t)NSLOTS * IDIM];   // silu(g)*u
__device__ int   g_counts[NE];
__device__ int   g_offsets[NE];
__device__ int   g_cursor[NE];
__device__ int   g_topi[T * 2];
__device__ float g_topw[T * 2];
__device__ int   g_tok[NSLOTS];
__device__ float g_sw[NSLOTS];
__device__ float g_psum[NE];
__device__ float g_zsum;

// ---------------- helpers ----------------
__device__ __forceinline__ u32 smem_u32(const void* p) {
    u32 a;
    asm("{ .reg .u64 t; cvta.to.shared.u64 t, %1; cvt.u32.u64 %0, t; }" : "=r"(a) : "l"(p));
    return a;
}
// row-major fp16 tile [128][32], 64B rows of 4 16B chunks, XOR swizzle
__device__ __forceinline__ u32 swoff(int row, int ch) {
    return (u32)(row * 64 + ((ch ^ ((row >> 1) & 3)) << 4));
}
__device__ __forceinline__ u32 packh(float lo, float hi) {  // low=f16rn(lo), high=f16rn(hi)
    u32 r;
    asm("cvt.rn.f16x2.f32 %0, %1, %2;" : "=r"(r) : "f"(hi), "f"(lo));
    return r;
}
// store 8 fp16 from two float4
__device__ __forceinline__ void sts_h(u32 addr, float4 v0, float4 v1) {
    u32 h0 = packh(v0.x, v0.y), h1 = packh(v0.z, v0.w);
    u32 h2 = packh(v1.x, v1.y), h3 = packh(v1.z, v1.w);
    asm volatile("st.shared.v4.b32 [%0], {%1,%2,%3,%4};"
                 :: "r"(addr), "r"(h0), "r"(h1), "r"(h2), "r"(h3) : "memory");
}
#define LDSM4(R, A)                                                             \
    asm volatile("ldmatrix.sync.aligned.m8n8.x4.shared.b16 {%0,%1,%2,%3}, [%4];" \
        : "=r"((R)[0]), "=r"((R)[1]), "=r"((R)[2]), "=r"((R)[3]) : "r"(A))

__device__ __forceinline__ void mma16816(float* d, const u32* a, const u32* b) {
    asm volatile(
        "mma.sync.aligned.m16n8k16.row.col.f32.f16.f16.f32 "
        "{%0,%1,%2,%3},{%4,%5,%6,%7},{%8,%9},{%0,%1,%2,%3};"
        : "+f"(d[0]), "+f"(d[1]), "+f"(d[2]), "+f"(d[3])
        : "r"(a[0]), "r"(a[1]), "r"(a[2]), "r"(a[3]), "r"(b[0]), "r"(b[1]));
}

// ---------------- small kernels ----------------
__global__ void reset_kernel() {
    int i = threadIdx.x;
    if (i < NE) { g_counts[i] = 0; g_cursor[i] = 0; g_psum[i] = 0.f; }
    if (i == 0) g_zsum = 0.f;
}

__global__ void router_kernel(const float* __restrict__ x,
                              const float* __restrict__ Wgate) {
    int t = blockIdx.x;
    const float* xr = x + (size_t)t * H;
    float p[NE];
#pragma unroll
    for (int e = 0; e < NE; ++e) p[e] = 0.f;
    for (int c = threadIdx.x; c < H; c += blockDim.x) {
        float xv = xr[c];
#pragma unroll
        for (int e = 0; e < NE; ++e) p[e] += xv * Wgate[e * H + c];
    }
    __shared__ float sm[NE][128];
#pragma unroll
    for (int e = 0; e < NE; ++e) sm[e][threadIdx.x] = p[e];
    __syncthreads();
    for (int s = 64; s > 0; s >>= 1) {
        if (threadIdx.x < s)
#pragma unroll
            for (int e = 0; e < NE; ++e)
                sm[e][threadIdx.x] += sm[e][threadIdx.x + s];
        __syncthreads();
    }
    if (threadIdx.x == 0) {
        float lg[NE];
#pragma unroll
        for (int e = 0; e < NE; ++e) lg[e] = sm[e][0];
        float mx = lg[0];
#pragma unroll
        for (int e = 1; e < NE; ++e) mx = fmaxf(mx, lg[e]);
        float se = 0.f, pr[NE];
#pragma unroll
        for (int e = 0; e < NE; ++e) { pr[e] = expf(lg[e] - mx); se += pr[e]; }
        float inv = 1.f / se;
#pragma unroll
        for (int e = 0; e < NE; ++e) pr[e] *= inv;
        int i0 = 0;
#pragma unroll
        for (int e = 1; e < NE; ++e) if (pr[e] > pr[i0]) i0 = e;
        int i1 = (i0 == 0) ? 1 : 0;
#pragma unroll
        for (int e = 0; e < NE; ++e)
            if (e != i0 && pr[e] > pr[i1]) i1 = e;
        float w0 = pr[i0], w1 = pr[i1];
        float ws = 1.f / (w0 + w1);
        g_topi[2 * t] = i0;     g_topw[2 * t] = w0 * ws;
        g_topi[2 * t + 1] = i1; g_topw[2 * t + 1] = w1 * ws;
        atomicAdd(&g_counts[i0], 1);
        atomicAdd(&g_counts[i1], 1);
#pragma unroll
        for (int e = 0; e < NE; ++e) atomicAdd(&g_psum[e], pr[e]);
        float lse = mx + logf(se);
        atomicAdd(&g_zsum, lse * lse);
    }
}

__global__ void finalize_kernel(float* __restrict__ out, int out_size) {
    if (threadIdx.x == 0 && blockIdx.x == 0) {
        int off = 0;
        for (int e = 0; e < NE; ++e) { g_offsets[e] = off; g_cursor[e] = off; off += g_counts[e]; }
        float aux = 0.f;
        for (int e = 0; e < NE; ++e)
            aux += (g_psum[e] / (float)T) * ((float)g_counts[e] / (float)(T * 2));
        aux *= (float)NE;
        float z = g_zsum / (float)T;
        if (out_size > T * H) out[(size_t)T * H] = 0.02f * aux + 0.001f * z;
    }
}

__global__ void assign_kernel() {
    int t = blockIdx.x * blockDim.x + threadIdx.x;
    if (t >= T) return;
#pragma unroll
    for (int k = 0; k < 2; ++k) {
        int e = g_topi[2 * t + k];
        int s = atomicAdd(&g_cursor[e], 1);
        g_tok[s] = t;
        g_sw[s] = g_topw[2 * t + k];
    }
}

// ---------------- single-term fp16 MMA GEMM ----------------
// D = f16(A) * f16(B), fp32 accumulate.
// MODE 0: A=x(gather), B=Wg  -> g_tmp (raw gate)
// MODE 1: A=x(gather), B=Wu  -> g_act = silu(g_tmp)*u
// MODE 2: A=g_act,     B=Wd  -> out[tok] += w * result (atomic)
template <int MODE>
__global__ __launch_bounds__(256)
void gemm_kernel(const float* __restrict__ Asrc, const float* __restrict__ W,
                 float* __restrict__ outp) {
    constexpr int KD = (MODE == 2) ? IDIM : H;
    constexpr int KT = KD / BK;

    int e = blockIdx.z;
    int cnt = g_counts[e];
    int m0 = blockIdx.x * BM;
    if (m0 >= cnt) return;
    int base = g_offsets[e];
    int n0 = blockIdx.y * BN;

    extern __shared__ char smem[];
    const float** aptr = (const float**)smem;   // 128 row pointers (1 KB)
    u32 tiles = smem_u32(smem) + 1024;          // 2 stages x 16 KB

    int tid = threadIdx.x, lane = tid & 31, wid = tid >> 5;
    int wm = wid & 3, wn = wid >> 2;

    if (tid < 128) {
        int r = m0 + tid;
        int slot = base + ((r < cnt) ? r : (cnt - 1));
        aptr[tid] = (MODE == 2) ? (g_act + (size_t)slot * IDIM)
                                : (Asrc + (size_t)g_tok[slot] * H);
    }
    __syncthreads();

    const float* wB = W + (size_t)e * ((size_t)IDIM * H) + (size_t)n0 * KD;

    int lr = tid >> 1;           // loader row 0..127
    int lc = (tid & 1) * 2;      // chunk base (chunk = 8 fp16 = 16B)
    const float* aRow = aptr[lr] + lc * 8;
    const float* bRow = wB + (size_t)lr * KD + lc * 8;
    u32 sA0 = swoff(lr, lc), sA1 = swoff(lr, lc + 1);

    // preload stage 0
    {
        float4 a0 = *(const float4*)(aRow);
        float4 a1 = *(const float4*)(aRow + 4);
        float4 a2 = *(const float4*)(aRow + 8);
        float4 a3 = *(const float4*)(aRow + 12);
        float4 b0 = *(const float4*)(bRow);
        float4 b1 = *(const float4*)(bRow + 4);
        float4 b2 = *(const float4*)(bRow + 8);
        float4 b3 = *(const float4*)(bRow + 12);
        sts_h(tiles + sA0, a0, a1);
        sts_h(tiles + sA1, a2, a3);
        sts_h(tiles + 8192 + sA0, b0, b1);
        sts_h(tiles + 8192 + sA1, b2, b3);
    }
    __syncthreads();

    float acc[2][8][4];
#pragma unroll
    for (int i = 0; i < 2; ++i)
#pragma unroll
        for (int j = 0; j < 8; ++j)
#pragma unroll
            for (int c = 0; c < 4; ++c) acc[i][j][c] = 0.f;

#pragma unroll 1
    for (int kt = 0; kt < KT; ++kt) {
        int b = kt & 1;
        u32 stage = tiles + b * STAGE;

        float4 pa0, pa1, pa2, pa3, pb0, pb1, pb2, pb3;
        bool pf = (kt + 1 < KT);
        if (pf) {
            int k0 = (kt + 1) * BK;
            pa0 = *(const float4*)(aRow + k0);
            pa1 = *(const float4*)(aRow + k0 + 4);
            pa2 = *(const float4*)(aRow + k0 + 8);
            pa3 = *(const float4*)(aRow + k0 + 12);
            pb0 = *(const float4*)(bRow + k0);
            pb1 = *(const float4*)(bRow + k0 + 4);
            pb2 = *(const float4*)(bRow + k0 + 8);
            pb3 = *(const float4*)(bRow + k0 + 12);
        }

#pragma unroll
        for (int ks = 0; ks < 2; ++ks) {
            u32 Ah[2][4];
#pragma unroll
            for (int mi = 0; mi < 2; ++mi) {
                int row = wm * 32 + mi * 16 + (lane & 15);
                int ch = ks * 2 + (lane >> 4);
                LDSM4(Ah[mi], stage + swoff(row, ch));
            }
#pragma unroll
            for (int p = 0; p < 4; ++p) {
                int row = wn * 64 + p * 16 + ((lane >> 4) << 3) + (lane & 7);
                int ch = ks * 2 + ((lane >> 3) & 1);
                u32 Bh[4];
                LDSM4(Bh, stage + 8192 + swoff(row, ch));
#pragma unroll
                for (int mi = 0; mi < 2; ++mi) {
                    mma16816(acc[mi][2 * p],     Ah[mi], Bh);
                    mma16816(acc[mi][2 * p + 1], Ah[mi], Bh + 2);
                }
            }
        }

        if (pf) {
            u32 ns = tiles + (b ^ 1) * STAGE;
            sts_h(ns + sA0, pa0, pa1);
            sts_h(ns + sA1, pa2, pa3);
            sts_h(ns + 8192 + sA0, pb0, pb1);
            sts_h(ns + 8192 + sA1, pb2, pb3);
        }
        __syncthreads();
    }

    // epilogue
    int rA = m0 + wm * 32 + (lane >> 2);
    int cA = n0 + wn * 64 + (lane & 3) * 2;
#pragma unroll
    for (int mi = 0; mi < 2; ++mi) {
#pragma unroll
        for (int ni = 0; ni < 8; ++ni) {
            int col = cA + ni * 8;
#pragma unroll
            for (int h = 0; h < 2; ++h) {
                int r = rA + mi * 16 + h * 8;
                if (r >= cnt) continue;
                float v0 = acc[mi][ni][2 * h], v1 = acc[mi][ni][2 * h + 1];
                int slot = base + r;
                if (MODE == 0) {
                    float2 o; o.x = v0; o.y = v1;
                    *(float2*)(g_tmp + (size_t)slot * IDIM + col) = o;
                } else if (MODE == 1) {
                    float2 g = *(const float2*)(g_tmp + (size_t)slot * IDIM + col);
                    float2 o;
                    o.x = g.x / (1.f + __expf(-g.x)) * v0;
                    o.y = g.y / (1.f + __expf(-g.y)) * v1;
                    *(float2*)(g_act + (size_t)slot * IDIM + col) = o;
                } else {
                    float w = g_sw[slot];
                    float* d = outp + (size_t)g_tok[slot] * H + col;
                    atomicAdd(d, w * v0);
                    atomicAdd(d + 1, w * v1);
                }
            }
        }
    }
}

// ---------------- launch ----------------
extern "C" void kernel_launch(void* const* d_in, const int* in_sizes, int n_in,
                              void* d_out, int out_size) {
    const float* x     = (const float*)d_in[0];
    const float* Wgate = (const float*)d_in[1];
    const float* Wg    = (const float*)d_in[2];
    const float* Wu    = (const float*)d_in[3];
    const float* Wd    = (const float*)d_in[4];
    float* out = (float*)d_out;

    cudaFuncSetAttribute(gemm_kernel<0>, cudaFuncAttributeMaxDynamicSharedMemorySize, SMEMSZ);
    cudaFuncSetAttribute(gemm_kernel<1>, cudaFuncAttributeMaxDynamicSharedMemorySize, SMEMSZ);
    cudaFuncSetAttribute(gemm_kernel<2>, cudaFuncAttributeMaxDynamicSharedMemorySize, SMEMSZ);

    cudaMemsetAsync(out, 0, (size_t)out_size * sizeof(float));
    reset_kernel<<<1, 32>>>();
    router_kernel<<<T, 128>>>(x, Wgate);
    finalize_kernel<<<1, 32>>>(out, out_size);
    assign_kernel<<<(T + 255) / 256, 256>>>();

    dim3 g1(T / BM, IDIM / BN, NE);   // (32, 44, 8)
    gemm_kernel<0><<<g1, 256, SMEMSZ>>>(x, Wg, out);
    gemm_kernel<1><<<g1, 256, SMEMSZ>>>(x, Wu, out);

    dim3 g2(T / BM, H / BN, NE);      // (32, 32, 8)
    gemm_kernel<2><<<g2, 256, SMEMSZ>>>(x, Wd, out);
}

// round 11
// speedup vs baseline: 5.4097x; 1.5208x over previous
#include <cuda_runtime.h>
#include <cuda_fp16.h>
#include <math.h>

typedef unsigned int u32;

#define H 4096
#define IDIM 5632
#define NE 8
#define T 4096
#define NSLOTS (T * 2)
#define BM 128
#define BN 128
#define BK 64
// stage: A 16KB @0 | B 16KB @16384 => 32KB; 3 stages
#define STAGE 32768
#define SMEMSZ (1024 + 3 * STAGE)

// ---------------- scratch (device globals; allocation-free) ----------------
__device__ __half g_hx[(size_t)T * H];
__device__ __half g_hwg[(size_t)NE * IDIM * H];
__device__ __half g_hwu[(size_t)NE * IDIM * H];
__device__ __half g_hwd[(size_t)NE * H * IDIM];
__device__ __half g_hact[(size_t)NSLOTS * IDIM];   // silu(g)*u, fp16
__device__ float  g_tmp[(size_t)NSLOTS * IDIM];    // raw gate values fp32
__device__ int    g_counts[NE];
__device__ int    g_offsets[NE];
__device__ int    g_cursor[NE];
__device__ int    g_topi[T * 2];
__device__ float  g_topw[T * 2];
__device__ int    g_tok[NSLOTS];
__device__ float  g_sw[NSLOTS];
__device__ float  g_psum[NE];
__device__ float  g_zsum;

// ---------------- helpers ----------------
__device__ __forceinline__ u32 smem_u32(const void* p) {
    u32 a;
    asm("{ .reg .u64 t; cvta.to.shared.u64 t, %1; cvt.u32.u64 %0, t; }" : "=r"(a) : "l"(p));
    return a;
}
// fp16 tile [128 rows][64 cols], 128B rows = 8 chunks of 16B, full XOR swizzle
__device__ __forceinline__ u32 swoff128(int row, int ch) {
    return (u32)(row * 128 + ((ch ^ (row & 7)) << 4));
}
__device__ __forceinline__ u32 packh(float lo, float hi) {
    u32 r;
    asm("cvt.rn.f16x2.f32 %0, %1, %2;" : "=r"(r) : "f"(hi), "f"(lo));
    return r;
}
#define CPASYNC(dst, src) \
    asm volatile("cp.async.cg.shared.global [%0], [%1], 16;" :: "r"(dst), "l"(src) : "memory")
#define CPCOMMIT() asm volatile("cp.async.commit_group;" ::: "memory")
#define CPWAIT1()  asm volatile("cp.async.wait_group 1;" ::: "memory")

#define LDSM4(R, A)                                                             \
    asm volatile("ldmatrix.sync.aligned.m8n8.x4.shared.b16 {%0,%1,%2,%3}, [%4];" \
        : "=r"((R)[0]), "=r"((R)[1]), "=r"((R)[2]), "=r"((R)[3]) : "r"(A))

__device__ __forceinline__ void mma16816(float* d, const u32* a, const u32* b) {
    asm volatile(
        "mma.sync.aligned.m16n8k16.row.col.f32.f16.f16.f32 "
        "{%0,%1,%2,%3},{%4,%5,%6,%7},{%8,%9},{%0,%1,%2,%3};"
        : "+f"(d[0]), "+f"(d[1]), "+f"(d[2]), "+f"(d[3])
        : "r"(a[0]), "r"(a[1]), "r"(a[2]), "r"(a[3]), "r"(b[0]), "r"(b[1]));
}

// ---------------- fp32 -> fp16 conversion pass ----------------
__global__ __launch_bounds__(256)
void cvt16(const float* __restrict__ s, __half* __restrict__ d, size_t n) {
    size_t i = ((size_t)blockIdx.x * 256 + threadIdx.x) * 8;
    if (i >= n) return;
    float4 v0 = *(const float4*)(s + i);
    float4 v1 = *(const float4*)(s + i + 4);
    uint4 o;
    o.x = packh(v0.x, v0.y); o.y = packh(v0.z, v0.w);
    o.z = packh(v1.x, v1.y); o.w = packh(v1.z, v1.w);
    *(uint4*)(d + i) = o;
}

// ---------------- small kernels ----------------
__global__ void reset_kernel() {
    int i = threadIdx.x;
    if (i < NE) { g_counts[i] = 0; g_cursor[i] = 0; g_psum[i] = 0.f; }
    if (i == 0) g_zsum = 0.f;
}

__global__ void router_kernel(const float* __restrict__ x,
                              const float* __restrict__ Wgate) {
    int t = blockIdx.x;
    const float* xr = x + (size_t)t * H;
    float p[NE];
#pragma unroll
    for (int e = 0; e < NE; ++e) p[e] = 0.f;
    for (int c = threadIdx.x; c < H; c += blockDim.x) {
        float xv = xr[c];
#pragma unroll
        for (int e = 0; e < NE; ++e) p[e] += xv * Wgate[e * H + c];
    }
    __shared__ float sm[NE][128];
#pragma unroll
    for (int e = 0; e < NE; ++e) sm[e][threadIdx.x] = p[e];
    __syncthreads();
    for (int s = 64; s > 0; s >>= 1) {
        if (threadIdx.x < s)
#pragma unroll
            for (int e = 0; e < NE; ++e)
                sm[e][threadIdx.x] += sm[e][threadIdx.x + s];
        __syncthreads();
    }
    if (threadIdx.x == 0) {
        float lg[NE];
#pragma unroll
        for (int e = 0; e < NE; ++e) lg[e] = sm[e][0];
        float mx = lg[0];
#pragma unroll
        for (int e = 1; e < NE; ++e) mx = fmaxf(mx, lg[e]);
        float se = 0.f, pr[NE];
#pragma unroll
        for (int e = 0; e < NE; ++e) { pr[e] = expf(lg[e] - mx); se += pr[e]; }
        float inv = 1.f / se;
#pragma unroll
        for (int e = 0; e < NE; ++e) pr[e] *= inv;
        int i0 = 0;
#pragma unroll
        for (int e = 1; e < NE; ++e) if (pr[e] > pr[i0]) i0 = e;
        int i1 = (i0 == 0) ? 1 : 0;
#pragma unroll
        for (int e = 0; e < NE; ++e)
            if (e != i0 && pr[e] > pr[i1]) i1 = e;
        float w0 = pr[i0], w1 = pr[i1];
        float ws = 1.f / (w0 + w1);
        g_topi[2 * t] = i0;     g_topw[2 * t] = w0 * ws;
        g_topi[2 * t + 1] = i1; g_topw[2 * t + 1] = w1 * ws;
        atomicAdd(&g_counts[i0], 1);
        atomicAdd(&g_counts[i1], 1);
#pragma unroll
        for (int e = 0; e < NE; ++e) atomicAdd(&g_psum[e], pr[e]);
        float lse = mx + logf(se);
        atomicAdd(&g_zsum, lse * lse);
    }
}

__global__ void finalize_kernel(float* __restrict__ out, int out_size) {
    if (threadIdx.x == 0 && blockIdx.x == 0) {
        int off = 0;
        for (int e = 0; e < NE; ++e) { g_offsets[e] = off; g_cursor[e] = off; off += g_counts[e]; }
        float aux = 0.f;
        for (int e = 0; e < NE; ++e)
            aux += (g_psum[e] / (float)T) * ((float)g_counts[e] / (float)(T * 2));
        aux *= (float)NE;
        float z = g_zsum / (float)T;
        if (out_size > T * H) out[(size_t)T * H] = 0.02f * aux + 0.001f * z;
    }
}

__global__ void assign_kernel() {
    int t = blockIdx.x * blockDim.x + threadIdx.x;
    if (t >= T) return;
#pragma unroll
    for (int k = 0; k < 2; ++k) {
        int e = g_topi[2 * t + k];
        int s = atomicAdd(&g_cursor[e], 1);
        g_tok[s] = t;
        g_sw[s] = g_topw[2 * t + k];
    }
}

// ---------------- fp16 MMA GEMM, cp.async 3-stage ----------------
// MODE 0: A=hx(gather), B=hwg -> g_tmp (raw gate, fp32)
// MODE 1: A=hx(gather), B=hwu -> g_hact = silu(g_tmp)*u (fp16)
// MODE 2: A=g_hact,     B=hwd -> out[tok] += w * result (atomic fp32)
template <int MODE>
__global__ __launch_bounds__(256, 2)
void gemm_kernel(const __half* __restrict__ Asrc, const __half* __restrict__ W,
                 float* __restrict__ outp) {
    constexpr int KD = (MODE == 2) ? IDIM : H;
    constexpr int KT = KD / BK;

    int e = blockIdx.z;
    int cnt = g_counts[e];
    int m0 = blockIdx.x * BM;
    if (m0 >= cnt) return;
    int base = g_offsets[e];
    int n0 = blockIdx.y * BN;

    extern __shared__ char smem[];
    const __half** aptr = (const __half**)smem;   // 128 row pointers (1 KB)
    u32 tiles = smem_u32(smem) + 1024;            // 3 stages x 32 KB

    int tid = threadIdx.x, lane = tid & 31, wid = tid >> 5;
    int wm = wid & 3, wn = wid >> 2;

    if (tid < 128) {
        int r = m0 + tid;
        int slot = base + ((r < cnt) ? r : (cnt - 1));
        aptr[tid] = (MODE == 2) ? (Asrc + (size_t)slot * IDIM)
                                : (Asrc + (size_t)g_tok[slot] * H);
    }
    __syncthreads();

    const __half* wB = W + (size_t)e * ((size_t)IDIM * H) + (size_t)n0 * KD;

    // loader: each thread copies 4 A chunks + 4 B chunks (16B each) per stage
    int lrow = tid >> 1, lch = (tid & 1) * 4;
    const __half* aRow = aptr[lrow] + lch * 8;
    const __half* bRow = wB + (size_t)lrow * KD + lch * 8;
    u32 so0 = swoff128(lrow, lch),     so1 = swoff128(lrow, lch + 1);
    u32 so2 = swoff128(lrow, lch + 2), so3 = swoff128(lrow, lch + 3);

#define ISSUE(sb, k0) do {                                  \
    u32 _s = (sb); int _k = (k0);                           \
    CPASYNC(_s + so0,         aRow + _k);                   \
    CPASYNC(_s + so1,         aRow + _k + 8);               \
    CPASYNC(_s + so2,         aRow + _k + 16);              \
    CPASYNC(_s + so3,         aRow + _k + 24);              \
    CPASYNC(_s + 16384 + so0, bRow + _k);                   \
    CPASYNC(_s + 16384 + so1, bRow + _k + 8);               \
    CPASYNC(_s + 16384 + so2, bRow + _k + 16);              \
    CPASYNC(_s + 16384 + so3, bRow + _k + 24);              \
} while (0)

    // prologue: stages 0 and 1
    ISSUE(tiles, 0);
    CPCOMMIT();
    ISSUE(tiles + STAGE, BK);
    CPCOMMIT();

    float acc[2][8][4];
#pragma unroll
    for (int i = 0; i < 2; ++i)
#pragma unroll
        for (int j = 0; j < 8; ++j)
#pragma unroll
            for (int c = 0; c < 4; ++c) acc[i][j][c] = 0.f;

#pragma unroll 1
    for (int kt = 0; kt < KT; ++kt) {
        CPWAIT1();
        __syncthreads();
        if (kt + 2 < KT) {
            int nslot = (kt + 2) % 3;
            ISSUE(tiles + nslot * STAGE, (kt + 2) * BK);
        }
        CPCOMMIT();

        u32 stage = tiles + (kt % 3) * STAGE;
#pragma unroll
        for (int ks = 0; ks < 4; ++ks) {
            u32 Ah[2][4];
#pragma unroll
            for (int mi = 0; mi < 2; ++mi) {
                int row = wm * 32 + mi * 16 + (lane & 15);
                int ch = ks * 2 + (lane >> 4);
                LDSM4(Ah[mi], stage + swoff128(row, ch));
            }
#pragma unroll
            for (int p = 0; p < 4; ++p) {
                int row = wn * 64 + p * 16 + ((lane >> 4) << 3) + (lane & 7);
                int ch = ks * 2 + ((lane >> 3) & 1);
                u32 Bh[4];
                LDSM4(Bh, stage + 16384 + swoff128(row, ch));
#pragma unroll
                for (int mi = 0; mi < 2; ++mi) {
                    mma16816(acc[mi][2 * p],     Ah[mi], Bh);
                    mma16816(acc[mi][2 * p + 1], Ah[mi], Bh + 2);
                }
            }
        }
    }
#undef ISSUE

    // epilogue
    int rA = m0 + wm * 32 + (lane >> 2);
    int cA = n0 + wn * 64 + (lane & 3) * 2;
#pragma unroll
    for (int mi = 0; mi < 2; ++mi) {
#pragma unroll
        for (int ni = 0; ni < 8; ++ni) {
            int col = cA + ni * 8;
#pragma unroll
            for (int h = 0; h < 2; ++h) {
                int r = rA + mi * 16 + h * 8;
                if (r >= cnt) continue;
                float v0 = acc[mi][ni][2 * h], v1 = acc[mi][ni][2 * h + 1];
                int slot = base + r;
                if (MODE == 0) {
                    float2 o; o.x = v0; o.y = v1;
                    *(float2*)(g_tmp + (size_t)slot * IDIM + col) = o;
                } else if (MODE == 1) {
                    float2 g = *(const float2*)(g_tmp + (size_t)slot * IDIM + col);
                    float ax = g.x / (1.f + __expf(-g.x)) * v0;
                    float ay = g.y / (1.f + __expf(-g.y)) * v1;
                    *(u32*)(g_hact + (size_t)slot * IDIM + col) = packh(ax, ay);
                } else {
                    float w = g_sw[slot];
                    float* d = outp + (size_t)g_tok[slot] * H + col;
                    atomicAdd(d, w * v0);
                    atomicAdd(d + 1, w * v1);
                }
            }
        }
    }
}

// ---------------- launch ----------------
extern "C" void kernel_launch(void* const* d_in, const int* in_sizes, int n_in,
                              void* d_out, int out_size) {
    const float* x     = (const float*)d_in[0];
    const float* Wgate = (const float*)d_in[1];
    const float* Wg    = (const float*)d_in[2];
    const float* Wu    = (const float*)d_in[3];
    const float* Wd    = (const float*)d_in[4];
    float* out = (float*)d_out;

    cudaFuncSetAttribute(gemm_kernel<0>, cudaFuncAttributeMaxDynamicSharedMemorySize, SMEMSZ);
    cudaFuncSetAttribute(gemm_kernel<1>, cudaFuncAttributeMaxDynamicSharedMemorySize, SMEMSZ);
    cudaFuncSetAttribute(gemm_kernel<2>, cudaFuncAttributeMaxDynamicSharedMemorySize, SMEMSZ);

    __half *hx, *hwg, *hwu, *hwd, *hact;
    cudaGetSymbolAddress((void**)&hx, g_hx);
    cudaGetSymbolAddress((void**)&hwg, g_hwg);
    cudaGetSymbolAddress((void**)&hwu, g_hwu);
    cudaGetSymbolAddress((void**)&hwd, g_hwd);
    cudaGetSymbolAddress((void**)&hact, g_hact);

    cudaMemsetAsync(out, 0, (size_t)out_size * sizeof(float));
    reset_kernel<<<1, 32>>>();
    router_kernel<<<T, 128>>>(x, Wgate);
    finalize_kernel<<<1, 32>>>(out, out_size);
    assign_kernel<<<(T + 255) / 256, 256>>>();

    // fp32 -> fp16 conversion passes (bit-identical to in-loop conversion)
    const size_t NW = (size_t)NE * IDIM * H;   // = NE*H*IDIM
    cvt16<<<(u32)(((size_t)T * H) / 2048), 256>>>(x, hx, (size_t)T * H);
    cvt16<<<(u32)(NW / 2048), 256>>>(Wg, hwg, NW);
    cvt16<<<(u32)(NW / 2048), 256>>>(Wu, hwu, NW);
    cvt16<<<(u32)(NW / 2048), 256>>>(Wd, hwd, NW);

    dim3 g1(T / BM, IDIM / BN, NE);   // (32, 44, 8)
    gemm_kernel<0><<<g1, 256, SMEMSZ>>>(hx, hwg, out);
    gemm_kernel<1><<<g1, 256, SMEMSZ>>>(hx, hwu, out);

    dim3 g2(T / BM, H / BN, NE);      // (32, 32, 8)
    gemm_kernel<2><<<g2, 256, SMEMSZ>>>(hact, hwd, out);
}